// round 10
// baseline (speedup 1.0000x reference)
#include <cuda_runtime.h>
#include <cstddef>
#include <cstdint>

#define BATCH 64
#define SEQ   2048
#define DIM   512
#define NFINE 16
#define MSPAN 512
#define GRID  (148 * 3)
#define NPAIR (BATCH * MSPAN / 2)

typedef unsigned long long u64;

// Blackwell packed fp32x2 math (SASS FFMA2/FADD2) — PTX-only.
#define FMA2(d,a,b,c) asm("fma.rn.f32x2 %0, %1, %2, %3;" : "=l"(d) : "l"(a), "l"(b), "l"(c))
#define ADD2(d,a,b)   asm("add.rn.f32x2 %0, %1, %2;" : "=l"(d) : "l"(a), "l"(b))

// Header: [0] = pair ticket (memset 0xFF -> starts at -1),
//         [4 + b] = span count of row b (-1 = not yet published).
__device__ int  g_hdr[4 + BATCH];
__device__ int2 g_spanPE[BATCH * MSPAN];  // static slots: (start,end) global tokens

__device__ __forceinline__ int acq_load(const int* p) {
    int v;
    asm volatile("ld.acquire.gpu.b32 %0, [%1];" : "=r"(v) : "l"(p) : "memory");
    return v;
}

// ---------------------------------------------------------------------------
// Tree-fold 4 per-lane partials across the warp in 6 SHFLs; lanes
// {0,8,16,24} write floc {0,1,2,3}.
// ---------------------------------------------------------------------------
__device__ __forceinline__ void fold_write(
    const float sc[4], float* __restrict__ dst, int lane)
{
    float send0 = (lane & 16) ? sc[0] : sc[2];
    float r0 = __shfl_xor_sync(0xffffffffu, send0, 16);
    float n0 = ((lane & 16) ? sc[2] : sc[0]) + r0;
    float send1 = (lane & 16) ? sc[1] : sc[3];
    float r1 = __shfl_xor_sync(0xffffffffu, send1, 16);
    float n1 = ((lane & 16) ? sc[3] : sc[1]) + r1;

    float send = (lane & 8) ? n0 : n1;
    float r = __shfl_xor_sync(0xffffffffu, send, 8);
    float v = ((lane & 8) ? n1 : n0) + r;

    v += __shfl_xor_sync(0xffffffffu, v, 4);
    v += __shfl_xor_sync(0xffffffffu, v, 2);
    v += __shfl_xor_sync(0xffffffffu, v, 1);

    if ((lane & 7) == 0) {
        int floc = (((lane >> 4) & 1) << 1) | ((lane >> 3) & 1);
        dst[floc] = v;
    }
}

// ---------------------------------------------------------------------------
// Segment-sum one span into 8 packed f32x2 regs (lane owns dims 4*lane+128j).
// ---------------------------------------------------------------------------
__device__ __forceinline__ void accum_span(
    u64 F[8], const float* __restrict__ hidden,
    const int* __restrict__ labels, int P, int E, int cI, int lane)
{
    {
        const ulonglong2* h =
            reinterpret_cast<const ulonglong2*>(hidden + (size_t)P * DIM);
        ulonglong2 a = __ldg(h + lane);
        ulonglong2 b = __ldg(h + lane + 32);
        ulonglong2 c = __ldg(h + lane + 64);
        ulonglong2 d = __ldg(h + lane + 96);
        F[0] = a.x; F[1] = a.y; F[2] = b.x; F[3] = b.y;
        F[4] = c.x; F[5] = c.y; F[6] = d.x; F[7] = d.y;
    }
    for (int s = P + 1; s < E; s += 32) {
        int ss = s + lane;
        bool hit = (ss < E) && (__ldg(labels + ss) == cI);
        unsigned m = __ballot_sync(0xffffffffu, hit);
        while (m) {
            int j = __ffs(m) - 1;
            m &= m - 1;
            const ulonglong2* h = reinterpret_cast<const ulonglong2*>(
                hidden + (size_t)(s + j) * DIM);
            ulonglong2 a = __ldg(h + lane);
            ulonglong2 b = __ldg(h + lane + 32);
            ulonglong2 c = __ldg(h + lane + 64);
            ulonglong2 d = __ldg(h + lane + 96);
            ADD2(F[0], F[0], a.x); ADD2(F[1], F[1], a.y);
            ADD2(F[2], F[2], b.x); ADD2(F[3], F[3], b.y);
            ADD2(F[4], F[4], c.x); ADD2(F[5], F[5], c.y);
            ADD2(F[6], F[6], d.x); ADD2(F[7], F[7], d.y);
        }
    }
}

// ---------------------------------------------------------------------------
// Fused kernel, per-row release/acquire (no global barrier).
// Blocks 0..63 index row b into static slots g_spanPE[b*MSPAN+k], publish
// nB[b]; all blocks then consume static 2-span tickets, spinning per-row
// (nearly always already published).
// ---------------------------------------------------------------------------
__global__ void __launch_bounds__(256, 4) fused_kernel(
    const float* __restrict__ hidden,
    const float* __restrict__ slot,   // [DIM][NFINE]
    const int*   __restrict__ labels, // flat [BATCH*SEQ]
    const int*   __restrict__ pB,
    const int*   __restrict__ pI,
    float* __restrict__ out)          // [BATCH][MSPAN][NFINE]
{
    __shared__ __align__(16) float Wsh[NFINE * DIM];  // Wsh[f*512 + d]
    __shared__ int Bpos[MSPAN + 1];
    __shared__ int wsum[8];

    const int tid  = threadIdx.x;
    const int lane = tid & 31;
    const int warp = tid >> 5;
    const int cI = *pI;

    // ---- phase 0: first 64 blocks index their batch row ----
    if (blockIdx.x < BATCH) {
        const int b = blockIdx.x;
        const int cB = *pB;
        const int4* row4 = reinterpret_cast<const int4*>(labels + (size_t)b * SEQ);

        int4 A = __ldg(row4 + 2 * tid);
        int4 Bv = __ldg(row4 + 2 * tid + 1);
        int lab[8] = {A.x, A.y, A.z, A.w, Bv.x, Bv.y, Bv.z, Bv.w};
        int flags[8];
        int cnt = 0;
#pragma unroll
        for (int j = 0; j < 8; j++) {
            flags[j] = (lab[j] == cB) ? 1 : 0;
            cnt += flags[j];
        }
        int inc = cnt;
#pragma unroll
        for (int o = 1; o < 32; o <<= 1) {
            int v = __shfl_up_sync(0xffffffffu, inc, o);
            if (lane >= o) inc += v;
        }
        if (lane == 31) wsum[warp] = inc;
        __syncthreads();
        if (tid < 8) {
            int v = wsum[tid];
#pragma unroll
            for (int o = 1; o < 8; o <<= 1) {
                int u = __shfl_up_sync(0xffu, v, o);
                if (tid >= o) v += u;
            }
            wsum[tid] = v;
        }
        __syncthreads();
        int excl = inc - cnt + (warp > 0 ? wsum[warp - 1] : 0);

        int idx = excl;
        const int s0 = tid * 8;
#pragma unroll
        for (int j = 0; j < 8; j++) {
            if (flags[j]) {
                if (idx <= MSPAN) Bpos[idx] = s0 + j;
                idx++;
            }
        }
        __syncthreads();
        int nbtot = wsum[7];
        int n = nbtot < MSPAN ? nbtot : MSPAN;
        for (int k = tid; k < n; k += 256) {
            int p = Bpos[k];
            int pend = (k + 1 < nbtot) ? Bpos[k + 1] : SEQ;
            g_spanPE[b * MSPAN + k] = make_int2(b * SEQ + p, b * SEQ + pend);
        }
        __syncthreads();
        if (tid == 0) {
            __threadfence();
            asm volatile("st.release.gpu.b32 [%0], %1;"
                         :: "l"(&g_hdr[4 + b]), "r"(n) : "memory");
        }
    }

    // ---- stage W transposed (all blocks) ----
    for (int i = tid; i < DIM * NFINE; i += 256) {
        int d = i >> 4;
        int f = i & 15;
        Wsh[f * DIM + d] = slot[i];
    }
    __syncthreads();
    const ulonglong2* W2 = reinterpret_cast<const ulonglong2*>(Wsh);

    // ---- main loop: static 2-span tickets with per-row acquire ----
    int cb = -1, cnb = 0;  // row-count cache
    for (;;) {
        int t;
        if (lane == 0) t = atomicAdd(&g_hdr[0], 1);
        t = __shfl_sync(0xffffffffu, t, 0) + 1;   // header starts at -1
        if (t >= NPAIR) break;

        const int w0 = 2 * t, w1 = w0 + 1;
        const int b0 = w0 >> 9, k0 = w0 & (MSPAN - 1);
        const int b1 = w1 >> 9, k1 = w1 & (MSPAN - 1);

        if (b0 != cb) {
            int nb = acq_load(&g_hdr[4 + b0]);
            while (nb < 0) nb = acq_load(&g_hdr[4 + b0]);
            cb = b0; cnb = nb;
        }
        int nb0 = cnb;
        int nb1 = nb0;
        if (b1 != b0) {
            int nb = acq_load(&g_hdr[4 + b1]);
            while (nb < 0) nb = acq_load(&g_hdr[4 + b1]);
            cb = b1; cnb = nb;
            nb1 = nb;
        }
        const bool v0 = (k0 < nb0);
        const bool v1 = (k1 < nb1);
        if (!v0 && !v1) continue;

        int2 pe0 = v0 ? __ldcg(&g_spanPE[w0]) : make_int2(0, 0);
        int2 pe1 = v1 ? __ldcg(&g_spanPE[w1]) : make_int2(0, 0);

        u64 F0[8], F1[8];
        if (v0) {
            accum_span(F0, hidden, labels, pe0.x, pe0.y, cI, lane);
        } else {
#pragma unroll
            for (int k = 0; k < 8; k++) F0[k] = 0ull;
        }
        if (v1) {
            accum_span(F1, hidden, labels, pe1.x, pe1.y, cI, lane);
        } else {
#pragma unroll
            for (int k = 0; k < 8; k++) F1[k] = 0ull;
        }

        // projection: 4 groups of 4 filters; W LDS shared by both spans
#pragma unroll
        for (int g = 0; g < 4; g++) {
            float sc0[4], sc1[4];
#pragma unroll
            for (int jj = 0; jj < 4; jj++) {
                const int f = 4 * g + jj;
                ulonglong2 wa = W2[f * 128 + lane];
                ulonglong2 wb = W2[f * 128 + lane + 32];
                ulonglong2 wc = W2[f * 128 + lane + 64];
                ulonglong2 wd = W2[f * 128 + lane + 96];
                u64 a0 = 0ull, a1 = 0ull;
                FMA2(a0, F0[0], wa.x, a0);  FMA2(a1, F1[0], wa.x, a1);
                FMA2(a0, F0[1], wa.y, a0);  FMA2(a1, F1[1], wa.y, a1);
                FMA2(a0, F0[2], wb.x, a0);  FMA2(a1, F1[2], wb.x, a1);
                FMA2(a0, F0[3], wb.y, a0);  FMA2(a1, F1[3], wb.y, a1);
                FMA2(a0, F0[4], wc.x, a0);  FMA2(a1, F1[4], wc.x, a1);
                FMA2(a0, F0[5], wc.y, a0);  FMA2(a1, F1[5], wc.y, a1);
                FMA2(a0, F0[6], wd.x, a0);  FMA2(a1, F1[6], wd.x, a1);
                FMA2(a0, F0[7], wd.y, a0);  FMA2(a1, F1[7], wd.y, a1);
                float2 p0 = *reinterpret_cast<float2*>(&a0);
                float2 p1 = *reinterpret_cast<float2*>(&a1);
                sc0[jj] = p0.x + p0.y;
                sc1[jj] = p1.x + p1.y;
            }
            if (v0) fold_write(sc0, out + (size_t)w0 * NFINE + 4 * g, lane);
            if (v1) fold_write(sc1, out + (size_t)w1 * NFINE + 4 * g, lane);
        }
    }
}

extern "C" void kernel_launch(void* const* d_in, const int* in_sizes, int n_in,
                              void* d_out, int out_size)
{
    const float* hidden = (const float*)d_in[0];
    const float* slot   = (const float*)d_in[1];
    const int*   labels = (const int*)d_in[2];
    const int*   pB     = (const int*)d_in[3];
    const int*   pI     = (const int*)d_in[4];
    float* out = (float*)d_out;

    void* hdr_ptr = nullptr;
    cudaGetSymbolAddress(&hdr_ptr, g_hdr);
    cudaMemsetAsync(hdr_ptr, 0xFF, (4 + BATCH) * sizeof(int), 0);
    cudaMemsetAsync(out, 0, (size_t)out_size * sizeof(float), 0);

    fused_kernel<<<GRID, 256>>>(hidden, slot, labels, pB, pI, out);
}

// round 11
// speedup vs baseline: 1.3649x; 1.3649x over previous
#include <cuda_runtime.h>
#include <cstddef>
#include <cstdint>

#define BATCH 64
#define SEQ   2048
#define DIM   512
#define NFINE 16
#define MSPAN 512
#define GRID  (148 * 4)

typedef unsigned long long u64;

// Blackwell packed fp32x2 math (SASS FFMA2/FADD2) — PTX-only.
#define FMA2(d,a,b,c) asm("fma.rn.f32x2 %0, %1, %2, %3;" : "=l"(d) : "l"(a), "l"(b), "l"(c))
#define ADD2(d,a,b)   asm("add.rn.f32x2 %0, %1, %2;" : "=l"(d) : "l"(a), "l"(b))

// [0]=total spans, [1]=work ticket, [2]=unused, [3]=index-done counter
__device__ int  g_ctr[4];
__device__ int2 g_spanPE[BATCH * MSPAN];  // (start, end) token, global indices
__device__ int  g_spanW [BATCH * MSPAN];  // output span slot (b*MSPAN + k)

__device__ __forceinline__ int acq_load(const int* p) {
    int v;
    asm volatile("ld.acquire.gpu.b32 %0, [%1];" : "=r"(v) : "l"(p) : "memory");
    return v;
}

// ---------------------------------------------------------------------------
// Tree-fold 4 per-lane partials across the warp in 6 SHFLs; lanes
// {0,8,16,24} write floc {0,1,2,3}.
// ---------------------------------------------------------------------------
__device__ __forceinline__ void fold_write(
    const float sc[4], float* __restrict__ dst, int lane)
{
    float send0 = (lane & 16) ? sc[0] : sc[2];
    float r0 = __shfl_xor_sync(0xffffffffu, send0, 16);
    float n0 = ((lane & 16) ? sc[2] : sc[0]) + r0;
    float send1 = (lane & 16) ? sc[1] : sc[3];
    float r1 = __shfl_xor_sync(0xffffffffu, send1, 16);
    float n1 = ((lane & 16) ? sc[3] : sc[1]) + r1;

    float send = (lane & 8) ? n0 : n1;
    float r = __shfl_xor_sync(0xffffffffu, send, 8);
    float v = ((lane & 8) ? n1 : n0) + r;

    v += __shfl_xor_sync(0xffffffffu, v, 4);
    v += __shfl_xor_sync(0xffffffffu, v, 2);
    v += __shfl_xor_sync(0xffffffffu, v, 1);

    if ((lane & 7) == 0) {
        int floc = (((lane >> 4) & 1) << 1) | ((lane >> 3) & 1);
        dst[floc] = v;
    }
}

// ---------------------------------------------------------------------------
// Segment-sum one span into 8 packed f32x2 regs (lane owns dims 4*lane+128j).
// ---------------------------------------------------------------------------
__device__ __forceinline__ void accum_span(
    u64 F[8], const float* __restrict__ hidden,
    const int* __restrict__ labels, int P, int E, int cI, int lane)
{
    {
        const ulonglong2* h =
            reinterpret_cast<const ulonglong2*>(hidden + (size_t)P * DIM);
        ulonglong2 a = __ldg(h + lane);
        ulonglong2 b = __ldg(h + lane + 32);
        ulonglong2 c = __ldg(h + lane + 64);
        ulonglong2 d = __ldg(h + lane + 96);
        F[0] = a.x; F[1] = a.y; F[2] = b.x; F[3] = b.y;
        F[4] = c.x; F[5] = c.y; F[6] = d.x; F[7] = d.y;
    }
    for (int s = P + 1; s < E; s += 32) {
        int ss = s + lane;
        bool hit = (ss < E) && (__ldg(labels + ss) == cI);
        unsigned m = __ballot_sync(0xffffffffu, hit);
        while (m) {
            int j = __ffs(m) - 1;
            m &= m - 1;
            const ulonglong2* h = reinterpret_cast<const ulonglong2*>(
                hidden + (size_t)(s + j) * DIM);
            ulonglong2 a = __ldg(h + lane);
            ulonglong2 b = __ldg(h + lane + 32);
            ulonglong2 c = __ldg(h + lane + 64);
            ulonglong2 d = __ldg(h + lane + 96);
            ADD2(F[0], F[0], a.x); ADD2(F[1], F[1], a.y);
            ADD2(F[2], F[2], b.x); ADD2(F[3], F[3], b.y);
            ADD2(F[4], F[4], c.x); ADD2(F[5], F[5], c.y);
            ADD2(F[6], F[6], d.x); ADD2(F[7], F[7], d.y);
        }
    }
}

// ---------------------------------------------------------------------------
// Fused kernel. Grid = 592 blocks, ALL resident (launch_bounds(256,4),
// 64 regs, 35KB smem -> exactly 4 blocks/SM). Blocks 0..63 build the
// compact worklist first, then everybody stages W, waits on the done
// counter, and consumes 2-span tickets.
// ---------------------------------------------------------------------------
__global__ void __launch_bounds__(256, 4) fused_kernel(
    const float* __restrict__ hidden,
    const float* __restrict__ slot,   // [DIM][NFINE]
    const int*   __restrict__ labels, // flat [BATCH*SEQ]
    const int*   __restrict__ pB,
    const int*   __restrict__ pI,
    float* __restrict__ out)          // [BATCH][MSPAN][NFINE]
{
    __shared__ __align__(16) float Wsh[NFINE * DIM];  // Wsh[f*512 + d], 32KB
    __shared__ int Bpos[MSPAN + 1];
    __shared__ int wsum[8];

    const int tid  = threadIdx.x;
    const int lane = tid & 31;
    const int warp = tid >> 5;

    // ---- phase 0: first 64 blocks build the worklist for batch row b ----
    if (blockIdx.x < BATCH) {
        const int b = blockIdx.x;
        const int cB = *pB;
        const int* row = labels + (size_t)b * SEQ;

        const int s0 = tid * 8;
        int flags[8];
        int cnt = 0;
#pragma unroll
        for (int j = 0; j < 8; j++) {
            flags[j] = (row[s0 + j] == cB) ? 1 : 0;
            cnt += flags[j];
        }
        int inc = cnt;
#pragma unroll
        for (int o = 1; o < 32; o <<= 1) {
            int v = __shfl_up_sync(0xffffffffu, inc, o);
            if (lane >= o) inc += v;
        }
        if (lane == 31) wsum[warp] = inc;
        __syncthreads();
        if (tid < 8) {
            int v = wsum[tid];
#pragma unroll
            for (int o = 1; o < 8; o <<= 1) {
                int u = __shfl_up_sync(0xffu, v, o);
                if (tid >= o) v += u;
            }
            wsum[tid] = v;
        }
        __syncthreads();
        int excl = inc - cnt + (warp > 0 ? wsum[warp - 1] : 0);

        int idx = excl;
#pragma unroll
        for (int j = 0; j < 8; j++) {
            if (flags[j]) {
                if (idx <= MSPAN) Bpos[idx] = s0 + j;
                idx++;
            }
        }
        __syncthreads();
        int nbtot = wsum[7];                       // total B tags in row
        int n = nbtot < MSPAN ? nbtot : MSPAN;
        __shared__ int s_base;
        if (tid == 0) s_base = atomicAdd(&g_ctr[0], n);
        __syncthreads();
        const int base = s_base;
        for (int k = tid; k < n; k += 256) {
            int p = Bpos[k];
            int pend = (k + 1 < nbtot) ? Bpos[k + 1] : SEQ;
            g_spanPE[base + k] = make_int2(b * SEQ + p, b * SEQ + pend);
            g_spanW[base + k]  = b * MSPAN + k;
        }
        __syncthreads();
        if (tid == 0) {
            __threadfence();                       // release worklist
            atomicAdd(&g_ctr[3], 1);
        }
    }

    // ---- stage W transposed while indexers finish ----
    for (int i = tid; i < DIM * NFINE; i += 256) {
        int d = i >> 4;
        int f = i & 15;
        Wsh[f * DIM + d] = slot[i];
    }

    // ---- wait until all 64 indexer blocks are done (acquire loads) ----
    if (tid == 0) {
        while (acq_load(&g_ctr[3]) < BATCH) { }
    }
    __syncthreads();

    const ulonglong2* W2 = reinterpret_cast<const ulonglong2*>(Wsh);
    const int cI = *pI;
    const int total = g_ctr[0];

    // ---- main loop: 2 spans per dynamic ticket ----
    for (;;) {
        int i;
        if (lane == 0) i = atomicAdd(&g_ctr[1], 2);
        i = __shfl_sync(0xffffffffu, i, 0);
        if (i >= total) break;
        const bool v1 = (i + 1 < total);

        int2 pe0 = __ldg(g_spanPE + i);
        int2 pe1 = v1 ? __ldg(g_spanPE + i + 1) : make_int2(pe0.x, pe0.x);
        const int O0 = __ldg(g_spanW + i);
        const int O1 = v1 ? __ldg(g_spanW + i + 1) : 0;

        u64 F0[8], F1[8];
        accum_span(F0, hidden, labels, pe0.x, pe0.y, cI, lane);
        if (v1) {
            accum_span(F1, hidden, labels, pe1.x, pe1.y, cI, lane);
        } else {
#pragma unroll
            for (int k = 0; k < 8; k++) F1[k] = 0ull;
        }

        // projection: 4 groups of 4 filters; W LDS shared by both spans
#pragma unroll
        for (int g = 0; g < 4; g++) {
            float sc0[4], sc1[4];
#pragma unroll
            for (int jj = 0; jj < 4; jj++) {
                const int f = 4 * g + jj;
                ulonglong2 wa = W2[f * 128 + lane];
                ulonglong2 wb = W2[f * 128 + lane + 32];
                ulonglong2 wc = W2[f * 128 + lane + 64];
                ulonglong2 wd = W2[f * 128 + lane + 96];
                u64 a0 = 0ull, a1 = 0ull;
                FMA2(a0, F0[0], wa.x, a0);  FMA2(a1, F1[0], wa.x, a1);
                FMA2(a0, F0[1], wa.y, a0);  FMA2(a1, F1[1], wa.y, a1);
                FMA2(a0, F0[2], wb.x, a0);  FMA2(a1, F1[2], wb.x, a1);
                FMA2(a0, F0[3], wb.y, a0);  FMA2(a1, F1[3], wb.y, a1);
                FMA2(a0, F0[4], wc.x, a0);  FMA2(a1, F1[4], wc.x, a1);
                FMA2(a0, F0[5], wc.y, a0);  FMA2(a1, F1[5], wc.y, a1);
                FMA2(a0, F0[6], wd.x, a0);  FMA2(a1, F1[6], wd.x, a1);
                FMA2(a0, F0[7], wd.y, a0);  FMA2(a1, F1[7], wd.y, a1);
                float2 p0 = *reinterpret_cast<float2*>(&a0);
                float2 p1 = *reinterpret_cast<float2*>(&a1);
                sc0[jj] = p0.x + p0.y;
                sc1[jj] = p1.x + p1.y;
            }
            fold_write(sc0, out + (size_t)O0 * NFINE + 4 * g, lane);
            if (v1) fold_write(sc1, out + (size_t)O1 * NFINE + 4 * g, lane);
        }
    }
}

extern "C" void kernel_launch(void* const* d_in, const int* in_sizes, int n_in,
                              void* d_out, int out_size)
{
    const float* hidden = (const float*)d_in[0];
    const float* slot   = (const float*)d_in[1];
    const int*   labels = (const int*)d_in[2];
    const int*   pB     = (const int*)d_in[3];
    const int*   pI     = (const int*)d_in[4];
    float* out = (float*)d_out;

    void* ctr_ptr = nullptr;
    cudaGetSymbolAddress(&ctr_ptr, g_ctr);
    cudaMemsetAsync(ctr_ptr, 0, 4 * sizeof(int), 0);
    cudaMemsetAsync(out, 0, (size_t)out_size * sizeof(float), 0);

    fused_kernel<<<GRID, 256>>>(hidden, slot, labels, pB, pI, out);
}

// round 12
// speedup vs baseline: 1.4755x; 1.0810x over previous
#include <cuda_runtime.h>
#include <cstddef>
#include <cstdint>

#define BATCH 64
#define SEQ   2048
#define DIM   512
#define NFINE 16
#define MSPAN 512
#define GRID  (148 * 3)

typedef unsigned long long u64;

// Blackwell packed fp32x2 math (SASS FFMA2/FADD2) — PTX-only.
#define FMA2(d,a,b,c) asm("fma.rn.f32x2 %0, %1, %2, %3;" : "=l"(d) : "l"(a), "l"(b), "l"(c))
#define ADD2(d,a,b)   asm("add.rn.f32x2 %0, %1, %2;" : "=l"(d) : "l"(a), "l"(b))

// [0]=total spans, [1]=work ticket, [2]=unused, [3]=index-done counter
__device__ int  g_ctr[4];
__device__ int2 g_spanSE[BATCH * MSPAN];  // (start,end) into g_tok (absolute)
__device__ int  g_spanW [BATCH * MSPAN];  // output span slot (b*MSPAN + k)
__device__ int  g_tok   [BATCH * SEQ];    // compact valid-token list (absolute token idx)

__device__ __forceinline__ int acq_load(const int* p) {
    int v;
    asm volatile("ld.acquire.gpu.b32 %0, [%1];" : "=r"(v) : "l"(p) : "memory");
    return v;
}

// ---------------------------------------------------------------------------
// Tree-fold 4 per-lane partials across the warp in 6 SHFLs; lanes
// {0,8,16,24} write floc {0,1,2,3}.
// ---------------------------------------------------------------------------
__device__ __forceinline__ void fold_write(
    const float sc[4], float* __restrict__ dst, int lane)
{
    float send0 = (lane & 16) ? sc[0] : sc[2];
    float r0 = __shfl_xor_sync(0xffffffffu, send0, 16);
    float n0 = ((lane & 16) ? sc[2] : sc[0]) + r0;
    float send1 = (lane & 16) ? sc[1] : sc[3];
    float r1 = __shfl_xor_sync(0xffffffffu, send1, 16);
    float n1 = ((lane & 16) ? sc[3] : sc[1]) + r1;

    float send = (lane & 8) ? n0 : n1;
    float r = __shfl_xor_sync(0xffffffffu, send, 8);
    float v = ((lane & 8) ? n1 : n0) + r;

    v += __shfl_xor_sync(0xffffffffu, v, 4);
    v += __shfl_xor_sync(0xffffffffu, v, 2);
    v += __shfl_xor_sync(0xffffffffu, v, 1);

    if ((lane & 7) == 0) {
        int floc = (((lane >> 4) & 1) << 1) | ((lane >> 3) & 1);
        dst[floc] = v;
    }
}

// ---------------------------------------------------------------------------
// Segment-sum over a precomputed token range [S,E) of g_tok. Counted loop,
// two rows in flight (8 independent LDG.128).
// ---------------------------------------------------------------------------
__device__ __forceinline__ void accum_span_list(
    u64 F[8], const float* __restrict__ hidden,
    const int* __restrict__ tok, int S, int E, int lane)
{
#pragma unroll
    for (int k = 0; k < 8; k++) F[k] = 0ull;

    for (int c = S; c < E; c += 32) {
        int t = 0;
        if (c + lane < E) t = __ldg(tok + c + lane);
        int n = E - c; if (n > 32) n = 32;
        int r = 0;
        for (; r + 2 <= n; r += 2) {
            int t0 = __shfl_sync(0xffffffffu, t, r);
            int t1 = __shfl_sync(0xffffffffu, t, r + 1);
            const ulonglong2* h0 =
                reinterpret_cast<const ulonglong2*>(hidden + (size_t)t0 * DIM);
            const ulonglong2* h1 =
                reinterpret_cast<const ulonglong2*>(hidden + (size_t)t1 * DIM);
            ulonglong2 a0 = __ldg(h0 + lane),      a1 = __ldg(h1 + lane);
            ulonglong2 b0 = __ldg(h0 + lane + 32), b1 = __ldg(h1 + lane + 32);
            ulonglong2 c0 = __ldg(h0 + lane + 64), c1 = __ldg(h1 + lane + 64);
            ulonglong2 d0 = __ldg(h0 + lane + 96), d1 = __ldg(h1 + lane + 96);
            ADD2(F[0], F[0], a0.x); ADD2(F[1], F[1], a0.y);
            ADD2(F[2], F[2], b0.x); ADD2(F[3], F[3], b0.y);
            ADD2(F[4], F[4], c0.x); ADD2(F[5], F[5], c0.y);
            ADD2(F[6], F[6], d0.x); ADD2(F[7], F[7], d0.y);
            ADD2(F[0], F[0], a1.x); ADD2(F[1], F[1], a1.y);
            ADD2(F[2], F[2], b1.x); ADD2(F[3], F[3], b1.y);
            ADD2(F[4], F[4], c1.x); ADD2(F[5], F[5], c1.y);
            ADD2(F[6], F[6], d1.x); ADD2(F[7], F[7], d1.y);
        }
        if (r < n) {
            int t0 = __shfl_sync(0xffffffffu, t, r);
            const ulonglong2* h0 =
                reinterpret_cast<const ulonglong2*>(hidden + (size_t)t0 * DIM);
            ulonglong2 a0 = __ldg(h0 + lane);
            ulonglong2 b0 = __ldg(h0 + lane + 32);
            ulonglong2 c0 = __ldg(h0 + lane + 64);
            ulonglong2 d0 = __ldg(h0 + lane + 96);
            ADD2(F[0], F[0], a0.x); ADD2(F[1], F[1], a0.y);
            ADD2(F[2], F[2], b0.x); ADD2(F[3], F[3], b0.y);
            ADD2(F[4], F[4], c0.x); ADD2(F[5], F[5], c0.y);
            ADD2(F[6], F[6], d0.x); ADD2(F[7], F[7], d0.y);
        }
    }
}

// ---------------------------------------------------------------------------
// Fused kernel. Blocks 0..63: index row b -> compact valid-token list +
// span ranges (two block scans). Then all blocks consume 2-span tickets:
// counted dual-row segment sum + shared-W projection.
// ---------------------------------------------------------------------------
__global__ void __launch_bounds__(256, 3) fused_kernel(
    const float* __restrict__ hidden,
    const float* __restrict__ slot,   // [DIM][NFINE]
    const int*   __restrict__ labels, // flat [BATCH*SEQ]
    const int*   __restrict__ pB,
    const int*   __restrict__ pI,
    float* __restrict__ out)          // [BATCH][MSPAN][NFINE]
{
    __shared__ __align__(16) float Wsh[NFINE * DIM];  // Wsh[f*512 + d], 32KB
    __shared__ int SpanStart[MSPAN];
    __shared__ int wsumA[8], wsumB[8];

    const int tid  = threadIdx.x;
    const int lane = tid & 31;
    const int warp = tid >> 5;

    // ---- phase 0: first 64 blocks index their batch row ----
    if (blockIdx.x < BATCH) {
        const int b = blockIdx.x;
        const int cB = *pB;
        const int cI = *pI;
        const int* row = labels + (size_t)b * SEQ;
        const int s0 = tid * 8;

        int flagB[8], isI[8];
        int cntB = 0;
#pragma unroll
        for (int j = 0; j < 8; j++) {
            int lab = row[s0 + j];
            flagB[j] = (lab == cB) ? 1 : 0;
            isI[j]   = (lab == cI) ? 1 : 0;
            cntB += flagB[j];
        }

        // scan 1: B counts
        int incB = cntB;
#pragma unroll
        for (int o = 1; o < 32; o <<= 1) {
            int v = __shfl_up_sync(0xffffffffu, incB, o);
            if (lane >= o) incB += v;
        }
        if (lane == 31) wsumA[warp] = incB;
        __syncthreads();
        if (tid < 8) {
            int v = wsumA[tid];
#pragma unroll
            for (int o = 1; o < 8; o <<= 1) {
                int u = __shfl_up_sync(0xffu, v, o);
                if (tid >= o) v += u;
            }
            wsumA[tid] = v;
        }
        __syncthreads();
        const int exclB = incB - cntB + (warp > 0 ? wsumA[warp - 1] : 0);
        const int nbtot = wsumA[7];

        // local validity with running B count
        int flagV[8];
        int cntV = 0;
        {
            int runB = exclB;
#pragma unroll
            for (int j = 0; j < 8; j++) {
                int v;
                if (flagB[j]) {
                    v = (runB < MSPAN) ? 1 : 0;
                    runB++;
                } else if (isI[j]) {
                    int seg = runB - 1;
                    v = (seg >= 0 && seg < MSPAN) ? 1 : 0;
                } else v = 0;
                flagV[j] = v;
                cntV += v;
            }
        }

        // scan 2: valid counts
        int incV = cntV;
#pragma unroll
        for (int o = 1; o < 32; o <<= 1) {
            int v = __shfl_up_sync(0xffffffffu, incV, o);
            if (lane >= o) incV += v;
        }
        if (lane == 31) wsumB[warp] = incV;
        __syncthreads();
        if (tid < 8) {
            int v = wsumB[tid];
#pragma unroll
            for (int o = 1; o < 8; o <<= 1) {
                int u = __shfl_up_sync(0xffu, v, o);
                if (tid >= o) v += u;
            }
            wsumB[tid] = v;
        }
        __syncthreads();
        const int exclV = incV - cntV + (warp > 0 ? wsumB[warp - 1] : 0);
        const int nvtot = wsumB[7];

        // emit tokens + span starts
        {
            int runB = exclB;
            int vidx = exclV;
#pragma unroll
            for (int j = 0; j < 8; j++) {
                if (flagB[j]) {
                    if (runB < MSPAN) SpanStart[runB] = vidx;
                    runB++;
                }
                if (flagV[j]) {
                    g_tok[b * SEQ + vidx] = b * SEQ + s0 + j;
                    vidx++;
                }
            }
        }
        __syncthreads();

        const int n = nbtot < MSPAN ? nbtot : MSPAN;
        __shared__ int s_base;
        if (tid == 0) s_base = atomicAdd(&g_ctr[0], n);
        __syncthreads();
        const int base = s_base;
        for (int k = tid; k < n; k += 256) {
            int S = SpanStart[k];
            int E = (k + 1 < n) ? SpanStart[k + 1] : nvtot;
            g_spanSE[base + k] = make_int2(b * SEQ + S, b * SEQ + E);
            g_spanW[base + k]  = b * MSPAN + k;
        }
        __syncthreads();
        if (tid == 0) {
            __threadfence();
            atomicAdd(&g_ctr[3], 1);
        }
    }

    // ---- stage W transposed while indexers finish ----
    for (int i = tid; i < DIM * NFINE; i += 256) {
        int d = i >> 4;
        int f = i & 15;
        Wsh[f * DIM + d] = slot[i];
    }

    // ---- wait until all 64 indexer blocks are done ----
    if (tid == 0) {
        while (acq_load(&g_ctr[3]) < BATCH) { }
    }
    __syncthreads();

    const ulonglong2* W2 = reinterpret_cast<const ulonglong2*>(Wsh);
    const int total = g_ctr[0];

    // ---- main loop: 2 spans per dynamic ticket ----
    for (;;) {
        int i;
        if (lane == 0) i = atomicAdd(&g_ctr[1], 2);
        i = __shfl_sync(0xffffffffu, i, 0);
        if (i >= total) break;
        const bool v1 = (i + 1 < total);

        int2 se0 = __ldg(g_spanSE + i);
        int2 se1 = v1 ? __ldg(g_spanSE + i + 1) : make_int2(0, 0);
        const int O0 = __ldg(g_spanW + i);
        const int O1 = v1 ? __ldg(g_spanW + i + 1) : 0;

        u64 F0[8], F1[8];
        accum_span_list(F0, hidden, g_tok, se0.x, se0.y, lane);
        if (v1) {
            accum_span_list(F1, hidden, g_tok, se1.x, se1.y, lane);
        } else {
#pragma unroll
            for (int k = 0; k < 8; k++) F1[k] = 0ull;
        }

        // projection: 4 groups of 4 filters; W LDS shared by both spans
#pragma unroll
        for (int g = 0; g < 4; g++) {
            float sc0[4], sc1[4];
#pragma unroll
            for (int jj = 0; jj < 4; jj++) {
                const int f = 4 * g + jj;
                ulonglong2 wa = W2[f * 128 + lane];
                ulonglong2 wb = W2[f * 128 + lane + 32];
                ulonglong2 wc = W2[f * 128 + lane + 64];
                ulonglong2 wd = W2[f * 128 + lane + 96];
                u64 a0 = 0ull, a1 = 0ull;
                FMA2(a0, F0[0], wa.x, a0);  FMA2(a1, F1[0], wa.x, a1);
                FMA2(a0, F0[1], wa.y, a0);  FMA2(a1, F1[1], wa.y, a1);
                FMA2(a0, F0[2], wb.x, a0);  FMA2(a1, F1[2], wb.x, a1);
                FMA2(a0, F0[3], wb.y, a0);  FMA2(a1, F1[3], wb.y, a1);
                FMA2(a0, F0[4], wc.x, a0);  FMA2(a1, F1[4], wc.x, a1);
                FMA2(a0, F0[5], wc.y, a0);  FMA2(a1, F1[5], wc.y, a1);
                FMA2(a0, F0[6], wd.x, a0);  FMA2(a1, F1[6], wd.x, a1);
                FMA2(a0, F0[7], wd.y, a0);  FMA2(a1, F1[7], wd.y, a1);
                float2 p0 = *reinterpret_cast<float2*>(&a0);
                float2 p1 = *reinterpret_cast<float2*>(&a1);
                sc0[jj] = p0.x + p0.y;
                sc1[jj] = p1.x + p1.y;
            }
            fold_write(sc0, out + (size_t)O0 * NFINE + 4 * g, lane);
            if (v1) fold_write(sc1, out + (size_t)O1 * NFINE + 4 * g, lane);
        }
    }
}

extern "C" void kernel_launch(void* const* d_in, const int* in_sizes, int n_in,
                              void* d_out, int out_size)
{
    const float* hidden = (const float*)d_in[0];
    const float* slot   = (const float*)d_in[1];
    const int*   labels = (const int*)d_in[2];
    const int*   pB     = (const int*)d_in[3];
    const int*   pI     = (const int*)d_in[4];
    float* out = (float*)d_out;

    void* ctr_ptr = nullptr;
    cudaGetSymbolAddress(&ctr_ptr, g_ctr);
    cudaMemsetAsync(ctr_ptr, 0, 4 * sizeof(int), 0);
    cudaMemsetAsync(out, 0, (size_t)out_size * sizeof(float), 0);

    fused_kernel<<<GRID, 256>>>(hidden, slot, labels, pB, pI, out);
}